// round 13
// baseline (speedup 1.0000x reference)
#include <cuda_runtime.h>
#include <cuda_fp16.h>
#include <cstdint>

#define N_USER 100000
#define N_ITEM 50000
#define NE     800000
#define NE4    (NE / 4)
#define H      128
#define N_TGT  8192

// ---------------------------------------------------------------------------
// Static device scratch (fp16 feature world)
// ---------------------------------------------------------------------------
__device__ __half g_eu16[N_USER * H];
__device__ __half g_ei16[N_ITEM * H];
__device__ __half g_xu0h[N_USER * H];
__device__ __half g_xi0h[N_ITEM * H];
__device__ __half g_xufh[N_TGT * H];
__device__ __half g_aggU[N_USER * 256];     // layer0: [mrev|mfol]; layer1: compact rows
__device__ __half g_aggI[N_ITEM * H];
__device__ unsigned g_wth[(128 + 192 + 192) * H];   // fp16 half2-packed K-major weights
__device__ float g_bias[3 * H];

// CSR + scan scratch. INVARIANT: g_cnt/g_bflag/g_ticket/bit arrays are ZERO at
// entry of every call (zero-init at load; re-zeroed by mlp tail blocks).
__device__ int g_cnt[3][N_USER + 1];
__device__ int g_off[5][N_USER + 1];
__device__ int g_cur[3][N_USER];
__device__ int g_csr[3][NE];
__device__ int g_bsum[5][128];
__device__ int g_bflag[5 * 128];
__device__ int g_ticket;

// pruning flags as bitmasks (L1-resident)
#define TB_W 4096
#define IB_W 2048
__device__ int g_tbits[TB_W];
__device__ int g_nUbits[TB_W];
__device__ int g_nIbits[IB_W];

__device__ int g_cmpU[N_USER];
__device__ int g_cmpI[N_ITEM];

// graph ids: 0 = buys (dst=item), 1 = rev (dst=user), 2 = fol (dst=user)

__device__ __forceinline__ int getbit(const int* a, int i) {
    return (__ldg(&a[i >> 5]) >> (i & 31)) & 1;
}
__device__ __forceinline__ void setbit(int* a, int i) {
    int w = i >> 5, m = 1 << (i & 31);
    if (!(a[w] & m)) atomicOr(&a[w], m);
}

__device__ __forceinline__ unsigned smem_u32(const void* p) {
    return (unsigned)__cvta_generic_to_shared(p);
}
#define CP16(dst, src, sz) \
    asm volatile("cp.async.cg.shared.global [%0], [%1], 16, %2;\n" \
                 :: "r"(dst), "l"(src), "r"(sz))

// ---------------------------------------------------------------------------
// K1: flag targets (tiny)
// ---------------------------------------------------------------------------
__global__ void flag_kernel(const int* __restrict__ tgt) {
    int i = blockIdx.x * blockDim.x + threadIdx.x;
    if (i < N_TGT) {
        int t = tgt[i];
        setbit(g_tbits, t);
        setbit(g_nUbits, t);
    }
}

// ---------------------------------------------------------------------------
// K2: fused [degree count + need flags] ++ [emb->fp16 + weight/bias prep]
// ---------------------------------------------------------------------------
#define NU8   (N_USER * H / 8)
#define NI8   (N_ITEM * H / 8)
#define WTOT  ((128 + 192 + 192) * H)
#define PREPN (NU8 + NI8 + WTOT + 3 * H)
#define CBLK  ((3 * NE4 + 255) / 256)
#define PBLK  ((PREPN + 255) / 256)

__device__ __forceinline__ uint4 pack8(float4 a, float4 b) {
    __half2 h0 = __floats2half2_rn(a.x, a.y);
    __half2 h1 = __floats2half2_rn(a.z, a.w);
    __half2 h2 = __floats2half2_rn(b.x, b.y);
    __half2 h3 = __floats2half2_rn(b.z, b.w);
    uint4 u;
    u.x = *(unsigned*)&h0; u.y = *(unsigned*)&h1;
    u.z = *(unsigned*)&h2; u.w = *(unsigned*)&h3;
    return u;
}
__device__ __forceinline__ float wval_item(const float* Wl, const float* Wr, int k, int j) {
    return (k < 128) ? Wr[(0 * H + j) * H + k] : Wl[(0 * H + j) * H + (k - 128)];
}
__device__ __forceinline__ float wval_user(const float* Wl, const float* Wr, int l, int k, int j) {
    if (k < 128) return Wr[((l * 3 + 1) * H + j) * H + k] + Wr[((l * 3 + 2) * H + j) * H + k];
    if (k < 256) return Wl[((l * 3 + 1) * H + j) * H + (k - 128)];
    return Wl[((l * 3 + 2) * H + j) * H + (k - 256)];
}

__global__ void count_prep_kernel(const int* __restrict__ d0,
                                  const int* __restrict__ d1, const int* __restrict__ s1,
                                  const int* __restrict__ d2, const int* __restrict__ s2,
                                  const float* __restrict__ eu, const float* __restrict__ ei,
                                  const float* __restrict__ Wl, const float* __restrict__ Wr,
                                  const float* __restrict__ bl) {
    if (blockIdx.x < CBLK) {
        int i = blockIdx.x * blockDim.x + threadIdx.x;
        if (i >= 3 * NE4) return;
        int g = i / NE4, j = i % NE4;
        if (g == 0) {
            int4 v = ((const int4*)d0)[j];
            atomicAdd(&g_cnt[0][v.x], 1);
            atomicAdd(&g_cnt[0][v.y], 1);
            atomicAdd(&g_cnt[0][v.z], 1);
            atomicAdd(&g_cnt[0][v.w], 1);
        } else if (g == 1) {
            int4 d = ((const int4*)d1)[j];
            int4 s = ((const int4*)s1)[j];
            atomicAdd(&g_cnt[1][d.x], 1);
            atomicAdd(&g_cnt[1][d.y], 1);
            atomicAdd(&g_cnt[1][d.z], 1);
            atomicAdd(&g_cnt[1][d.w], 1);
            if (getbit(g_tbits, d.x)) setbit(g_nIbits, s.x);
            if (getbit(g_tbits, d.y)) setbit(g_nIbits, s.y);
            if (getbit(g_tbits, d.z)) setbit(g_nIbits, s.z);
            if (getbit(g_tbits, d.w)) setbit(g_nIbits, s.w);
        } else {
            int4 d = ((const int4*)d2)[j];
            int4 s = ((const int4*)s2)[j];
            atomicAdd(&g_cnt[2][d.x], 1);
            atomicAdd(&g_cnt[2][d.y], 1);
            atomicAdd(&g_cnt[2][d.z], 1);
            atomicAdd(&g_cnt[2][d.w], 1);
            if (getbit(g_tbits, d.x)) setbit(g_nUbits, s.x);
            if (getbit(g_tbits, d.y)) setbit(g_nUbits, s.y);
            if (getbit(g_tbits, d.z)) setbit(g_nUbits, s.z);
            if (getbit(g_tbits, d.w)) setbit(g_nUbits, s.w);
        }
        return;
    }
    // ---- prep part ----
    int i = (blockIdx.x - CBLK) * blockDim.x + threadIdx.x;
    if (i < NU8) {
        float4 a = ((const float4*)eu)[2 * i], b = ((const float4*)eu)[2 * i + 1];
        ((uint4*)g_eu16)[i] = pack8(a, b);
        return;
    }
    int j = i - NU8;
    if (j < NI8) {
        float4 a = ((const float4*)ei)[2 * j], b = ((const float4*)ei)[2 * j + 1];
        ((uint4*)g_ei16)[j] = pack8(a, b);
        return;
    }
    j -= NI8;
    if (j < WTOT) {
        float v0, v1;
        if (j < 128 * H) {
            int k2 = j >> 7, c = j & 127;
            v0 = wval_item(Wl, Wr, 2 * k2, c);
            v1 = wval_item(Wl, Wr, 2 * k2 + 1, c);
        } else {
            int rel = j - 128 * H;
            int l = (rel < 192 * H) ? 0 : 1;
            if (l == 1) rel -= 192 * H;
            int k2 = rel >> 7, c = rel & 127;
            v0 = wval_user(Wl, Wr, l, 2 * k2, c);
            v1 = wval_user(Wl, Wr, l, 2 * k2 + 1, c);
        }
        __half2 h = __floats2half2_rn(v0, v1);
        g_wth[j] = *(unsigned*)&h;
        return;
    }
    j -= WTOT;
    if (j < 3 * H) {
        int slot = j >> 7, c = j & 127;
        float b;
        if (slot == 0)      b = bl[0 * H + c];
        else if (slot == 1) b = bl[1 * H + c] + bl[2 * H + c];
        else                b = bl[(3 + 1) * H + c] + bl[(3 + 2) * H + c];
        g_bias[j] = b;
    }
}

// ---------------------------------------------------------------------------
// K3: single-pass scan over 5 rows with ticket-ordered parallel lookback.
// ---------------------------------------------------------------------------
#define NB_I 49
#define NB_U 98
#define SCAN_BLOCKS (NB_I + NB_U + NB_U + NB_U + NB_I)

__device__ __forceinline__ int scan_n(int g) {
    return (g == 0 || g == 4) ? N_ITEM : N_USER;
}

__global__ void scan_kernel() {
    __shared__ int s_g, s_b;
    __shared__ int warp_sums[32];
    __shared__ int sw[4];
    __shared__ int s_base;

    if (threadIdx.x == 0) {
        int v = atomicAdd(&g_ticket, 1);
        int g, b;
        if (v < NB_I)                         { g = 0; b = v; }
        else if (v < NB_I + NB_U)             { g = 1; b = v - NB_I; }
        else if (v < NB_I + 2 * NB_U)         { g = 2; b = v - NB_I - NB_U; }
        else if (v < NB_I + 3 * NB_U)         { g = 3; b = v - NB_I - 2 * NB_U; }
        else                                  { g = 4; b = v - NB_I - 3 * NB_U; }
        s_g = g; s_b = b;
    }
    __syncthreads();
    int g = s_g, b = s_b;
    int n = scan_n(g);
    int nb = (g == 0 || g == 4) ? NB_I : NB_U;

    int i = b * 1024 + (int)threadIdx.x;
    int v;
    if (i >= n) v = 0;
    else if (g < 3) v = g_cnt[g][i];
    else if (g == 3) v = getbit(g_nUbits, i);
    else v = getbit(g_nIbits, i);

    int lane = threadIdx.x & 31, wid = threadIdx.x >> 5;
    int x = v;
    #pragma unroll
    for (int s = 1; s < 32; s <<= 1) {
        int y = __shfl_up_sync(0xffffffffu, x, s);
        if (lane >= s) x += y;
    }
    if (lane == 31) warp_sums[wid] = x;
    __syncthreads();
    if (wid == 0) {
        int w = warp_sums[lane];
        int xw = w;
        #pragma unroll
        for (int s = 1; s < 32; s <<= 1) {
            int y = __shfl_up_sync(0xffffffffu, xw, s);
            if (lane >= s) xw += y;
        }
        warp_sums[lane] = xw - w;
    }
    __syncthreads();
    int incl = x + warp_sums[wid];

    if (threadIdx.x == 1023) {
        g_bsum[g][b] = incl;
        __threadfence();
        atomicExch(&g_bflag[g * 128 + b], 1);
    }

    if (threadIdx.x < 128) {
        int j = threadIdx.x;
        int pv = 0;
        if (j < b) {
            while (atomicAdd(&g_bflag[g * 128 + j], 0) == 0) { }
            pv = g_bsum[g][j];
        }
        #pragma unroll
        for (int o = 16; o; o >>= 1) pv += __shfl_xor_sync(0xffffffffu, pv, o);
        if (lane == 0) sw[j >> 5] = pv;
    }
    __syncthreads();
    if (threadIdx.x == 0) s_base = sw[0] + sw[1] + sw[2] + sw[3];
    __syncthreads();
    int base = s_base;

    if (threadIdx.x == 1023 && b == nb - 1) g_off[g][n] = base + incl;
    if (i >= n) return;
    int val = base + incl - v;
    if (g < 3) {
        g_off[g][i] = val;
        g_cur[g][i] = val;
    } else if (g == 3) {
        if (v) g_cmpU[val] = i;
    } else {
        if (v) g_cmpI[val] = i;
    }
}

// ---------------------------------------------------------------------------
// K4: filtered fill — only edges whose dst node is ever read downstream.
// ---------------------------------------------------------------------------
__global__ void fill_all_kernel(const int* __restrict__ d0, const int* __restrict__ s0,
                                const int* __restrict__ d1, const int* __restrict__ s1,
                                const int* __restrict__ d2, const int* __restrict__ s2) {
    int i = blockIdx.x * blockDim.x + threadIdx.x;
    if (i >= 3 * NE4) return;
    int g = i / NE4, j = i % NE4;
    const int* d = (g == 0) ? d0 : (g == 1) ? d1 : d2;
    const int* s = (g == 0) ? s0 : (g == 1) ? s1 : s2;
    const int* need = (g == 0) ? g_nIbits : g_nUbits;
    int4 dv = ((const int4*)d)[j];
    int4 sv = ((const int4*)s)[j];
    if (getbit(need, dv.x)) g_csr[g][atomicAdd(&g_cur[g][dv.x], 1)] = sv.x;
    if (getbit(need, dv.y)) g_csr[g][atomicAdd(&g_cur[g][dv.y], 1)] = sv.y;
    if (getbit(need, dv.z)) g_csr[g][atomicAdd(&g_cur[g][dv.z], 1)] = sv.z;
    if (getbit(need, dv.w)) g_csr[g][atomicAdd(&g_cur[g][dv.w], 1)] = sv.w;
}

// ---------------------------------------------------------------------------
// Gather-mean over fp16 rows (fp32 accumulate, strict index order).
// ---------------------------------------------------------------------------
__device__ __forceinline__ void acc4(float4& a, uint2 u) {
    __half2 h0 = *(__half2*)&u.x, h1 = *(__half2*)&u.y;
    float2 f0 = __half22float2(h0), f1 = __half22float2(h1);
    a.x += f0.x; a.y += f0.y; a.z += f1.x; a.w += f1.y;
}

__device__ __forceinline__ void agg_one(int g, int node, int lane,
                                        const __half* __restrict__ src,
                                        __half* __restrict__ dst) {
    int s = g_off[g][node], e = g_off[g][node + 1];
    const int* lst = g_csr[g];
    float4 acc = make_float4(0.f, 0.f, 0.f, 0.f);
    int i = s;
    for (; i + 8 <= e; i += 8) {
        uint2 v0 = *(const uint2*)(src + (size_t)lst[i]     * H + lane * 4);
        uint2 v1 = *(const uint2*)(src + (size_t)lst[i + 1] * H + lane * 4);
        uint2 v2 = *(const uint2*)(src + (size_t)lst[i + 2] * H + lane * 4);
        uint2 v3 = *(const uint2*)(src + (size_t)lst[i + 3] * H + lane * 4);
        uint2 v4 = *(const uint2*)(src + (size_t)lst[i + 4] * H + lane * 4);
        uint2 v5 = *(const uint2*)(src + (size_t)lst[i + 5] * H + lane * 4);
        uint2 v6 = *(const uint2*)(src + (size_t)lst[i + 6] * H + lane * 4);
        uint2 v7 = *(const uint2*)(src + (size_t)lst[i + 7] * H + lane * 4);
        acc4(acc, v0); acc4(acc, v1); acc4(acc, v2); acc4(acc, v3);
        acc4(acc, v4); acc4(acc, v5); acc4(acc, v6); acc4(acc, v7);
    }
    for (; i + 4 <= e; i += 4) {
        uint2 v0 = *(const uint2*)(src + (size_t)lst[i]     * H + lane * 4);
        uint2 v1 = *(const uint2*)(src + (size_t)lst[i + 1] * H + lane * 4);
        uint2 v2 = *(const uint2*)(src + (size_t)lst[i + 2] * H + lane * 4);
        uint2 v3 = *(const uint2*)(src + (size_t)lst[i + 3] * H + lane * 4);
        acc4(acc, v0); acc4(acc, v1); acc4(acc, v2); acc4(acc, v3);
    }
    for (; i < e; i++) {
        uint2 v0 = *(const uint2*)(src + (size_t)lst[i] * H + lane * 4);
        acc4(acc, v0);
    }
    float inv = (e > s) ? 1.0f / (float)(e - s) : 0.0f;
    __half2 o0 = __floats2half2_rn(acc.x * inv, acc.y * inv);
    __half2 o1 = __floats2half2_rn(acc.z * inv, acc.w * inv);
    uint2 o; o.x = *(unsigned*)&o0; o.y = *(unsigned*)&o1;
    *(uint2*)(dst + lane * 4) = o;
}

__global__ void agg_l0_kernel(const __half* __restrict__ eu,
                              const __half* __restrict__ ei) {
    int warp = (blockIdx.x * blockDim.x + threadIdx.x) >> 5;
    int lane = threadIdx.x & 31;
    if (warp < N_ITEM) {
        int nI = __ldg(&g_off[4][N_ITEM]);
        if (warp >= nI) return;
        int node = g_cmpI[warp];
        agg_one(0, node, lane, eu, g_aggI + (size_t)node * H);
    } else {
        int w2 = warp - N_ITEM;
        int nU = __ldg(&g_off[3][N_USER]);
        if (w2 < N_USER) {
            if (w2 >= nU) return;
            int node = g_cmpU[w2];
            agg_one(1, node, lane, ei, g_aggU + (size_t)node * 256);
        } else {
            w2 -= N_USER;
            if (w2 >= N_USER || w2 >= nU) return;
            int node = g_cmpU[w2];
            agg_one(2, node, lane, eu, g_aggU + (size_t)node * 256 + 128);
        }
    }
}

__global__ void agg_tgt_kernel(const __half* __restrict__ xi0,
                               const __half* __restrict__ xu0,
                               const int* __restrict__ tgt) {
    int warp = (blockIdx.x * blockDim.x + threadIdx.x) >> 5;
    int lane = threadIdx.x & 31;
    if (warp >= 2 * N_TGT) return;
    int pos = warp & (N_TGT - 1);
    int node = tgt[pos];
    if (warp < N_TGT)
        agg_one(1, node, lane, xi0, g_aggU + (size_t)pos * 256);
    else
        agg_one(2, node, lane, xu0, g_aggU + (size_t)pos * 256 + 128);
}

// ---------------------------------------------------------------------------
// FP16 mma.sync tensor-core GEMM (cp.async 3-stage) + fused LN + ReLU.
// (tcgen05 is unavailable: harness PTX targets compute_103, not compute_103a.)
// ---------------------------------------------------------------------------
#define ASTRIDE 36
#define WSTRIDE 136
#define OSTRIDE 132
#define STAGEB  35840

extern __shared__ char g_smraw[];

struct GemmJob {
    __half* out;
    const __half* A0;
    const __half* A1;
    const int* ridx0;
    const int* ridx1;
    const int* ridxo;
    const int* cnt;
    const unsigned* Wt;
    const float* bias;
    const float* gam;
    const float* bet;
    int lda0, lda1, k0c, nchunk, nrows;
};

__device__ __forceinline__ void mma_f16(float c[4], const unsigned a[4], const unsigned b[2]) {
    asm volatile(
        "mma.sync.aligned.m16n8k16.row.col.f32.f16.f16.f32 "
        "{%0,%1,%2,%3}, {%4,%5,%6,%7}, {%8,%9}, {%0,%1,%2,%3};"
        : "+f"(c[0]), "+f"(c[1]), "+f"(c[2]), "+f"(c[3])
        : "r"(a[0]), "r"(a[1]), "r"(a[2]), "r"(a[3]), "r"(b[0]), "r"(b[1]));
}

__global__ void __launch_bounds__(256, 2) gemm_ln_kernel(GemmJob j0, GemmJob j1, int split) {
    GemmJob J = (blockIdx.x < (unsigned)split) ? j0 : j1;
    int bid = (blockIdx.x < (unsigned)split) ? blockIdx.x : blockIdx.x - split;
    int row0 = bid * 128;

    int nrows = J.cnt ? __ldg(J.cnt) : J.nrows;
    if (row0 >= nrows) return;

    int t = threadIdx.x;
    int lane = t & 31;
    int wid = t >> 5;
    int warp_m = wid & 3;
    int warp_n = wid >> 2;
    int gid = lane >> 2;
    int tig = lane & 3;

    float c[2][8][4];
    #pragma unroll
    for (int nt = 0; nt < 8; nt++) {
        int col = warp_n * 64 + nt * 8 + 2 * tig;
        float b0 = J.bias[col], b1 = J.bias[col + 1];
        #pragma unroll
        for (int mt = 0; mt < 2; mt++) {
            c[mt][nt][0] = b0; c[mt][nt][1] = b1;
            c[mt][nt][2] = b0; c[mt][nt][3] = b1;
        }
    }

    auto load_chunk = [&](int ck, int st) {
        if (ck < J.nchunk) {
            const __half* A; int lda, cb; const int* ridx;
            if (ck < J.k0c) { A = J.A0; lda = J.lda0; cb = ck * 64; ridx = J.ridx0; }
            else            { A = J.A1; lda = J.lda1; cb = (ck - J.k0c) * 64; ridx = J.ridx1; }
            unsigned* As = (unsigned*)(g_smraw + st * STAGEB);
            #pragma unroll
            for (int i2 = 0; i2 < 4; i2++) {
                int idx = t + 256 * i2;
                int r = idx >> 3, u = idx & 7;
                int base = row0 + r;
                int ok = (base < nrows);
                if (!ok) base = row0;
                int row = ridx ? __ldg(ridx + base) : base;
                const __half* src = A + (size_t)row * lda + cb + u * 8;
                CP16(smem_u32(As + r * ASTRIDE + u * 4), src, ok ? 16 : 0);
            }
            unsigned* Ws = (unsigned*)(g_smraw + st * STAGEB + 128 * ASTRIDE * 4);
            #pragma unroll
            for (int i2 = 0; i2 < 4; i2++) {
                int idx = t + 256 * i2;
                int rr = idx >> 5, u = idx & 31;
                const unsigned* src = J.Wt + (size_t)(ck * 32 + rr) * H + u * 4;
                CP16(smem_u32(Ws + rr * WSTRIDE + u * 4), src, 16);
            }
        }
        asm volatile("cp.async.commit_group;\n" ::);
    };

    load_chunk(0, 0);
    load_chunk(1, 1);

    for (int ck = 0; ck < J.nchunk; ck++) {
        asm volatile("cp.async.wait_group 1;\n" ::);
        __syncthreads();
        load_chunk(ck + 2, (ck + 2) % 3);

        int st = ck % 3;
        const unsigned* As = (const unsigned*)(g_smraw + st * STAGEB);
        const unsigned* Ws = (const unsigned*)(g_smraw + st * STAGEB + 128 * ASTRIDE * 4);
        #pragma unroll
        for (int ks = 0; ks < 4; ks++) {
            int k2 = ks * 8;
            unsigned a[2][4];
            #pragma unroll
            for (int mt = 0; mt < 2; mt++) {
                int r = warp_m * 32 + mt * 16 + gid;
                a[mt][0] = As[r * ASTRIDE + k2 + tig];
                a[mt][1] = As[(r + 8) * ASTRIDE + k2 + tig];
                a[mt][2] = As[r * ASTRIDE + k2 + tig + 4];
                a[mt][3] = As[(r + 8) * ASTRIDE + k2 + tig + 4];
            }
            unsigned b[8][2];
            #pragma unroll
            for (int nt = 0; nt < 8; nt++) {
                int cc = warp_n * 64 + nt * 8 + gid;
                b[nt][0] = Ws[(k2 + tig) * WSTRIDE + cc];
                b[nt][1] = Ws[(k2 + tig + 4) * WSTRIDE + cc];
            }
            #pragma unroll
            for (int mt = 0; mt < 2; mt++)
                #pragma unroll
                for (int nt = 0; nt < 8; nt++)
                    mma_f16(c[mt][nt], a[mt], b[nt]);
        }
    }

    // ---- epilogue: stage fp32 to smem, fused LayerNorm + ReLU, fp16 out ----
    asm volatile("cp.async.wait_group 0;\n" ::);
    __syncthreads();
    float* Osm = (float*)g_smraw;
    #pragma unroll
    for (int mt = 0; mt < 2; mt++) {
        #pragma unroll
        for (int nt = 0; nt < 8; nt++) {
            int col = warp_n * 64 + nt * 8 + 2 * tig;
            int r = warp_m * 32 + mt * 16 + gid;
            *(float2*)(Osm + r * OSTRIDE + col)       = make_float2(c[mt][nt][0], c[mt][nt][1]);
            *(float2*)(Osm + (r + 8) * OSTRIDE + col) = make_float2(c[mt][nt][2], c[mt][nt][3]);
        }
    }
    __syncthreads();

    float4 gg = *(const float4*)(J.gam + lane * 4);
    float4 bb = *(const float4*)(J.bet + lane * 4);
    #pragma unroll
    for (int i = 0; i < 16; i++) {
        int r = wid * 16 + i;
        int base = row0 + r;
        if (base >= nrows) break;
        float4 v = *(float4*)(Osm + r * OSTRIDE + lane * 4);
        float s1 = v.x + v.y + v.z + v.w;
        float s2 = v.x * v.x + v.y * v.y + v.z * v.z + v.w * v.w;
        #pragma unroll
        for (int o = 16; o; o >>= 1) {
            s1 += __shfl_xor_sync(0xffffffffu, s1, o);
            s2 += __shfl_xor_sync(0xffffffffu, s2, o);
        }
        float mu = s1 * (1.0f / H);
        float var = s2 * (1.0f / H) - mu * mu;
        float rs = rsqrtf(var + 1e-5f);
        float ox = fmaxf((v.x - mu) * rs * gg.x + bb.x, 0.f);
        float oy = fmaxf((v.y - mu) * rs * gg.y + bb.y, 0.f);
        float oz = fmaxf((v.z - mu) * rs * gg.z + bb.z, 0.f);
        float ow = fmaxf((v.w - mu) * rs * gg.w + bb.w, 0.f);
        __half2 h0 = __floats2half2_rn(ox, oy);
        __half2 h1 = __floats2half2_rn(oz, ow);
        uint2 o; o.x = *(unsigned*)&h0; o.y = *(unsigned*)&h1;
        int orow = J.ridxo ? __ldg(J.ridxo + base) : base;
        *(uint2*)(J.out + (size_t)orow * H + lane * 4) = o;
    }
}

// ---------------------------------------------------------------------------
// K-last: zero-tail blocks FIRST, then MLP head (W1/b1/W2 staged in smem).
// ---------------------------------------------------------------------------
#define MLP_BLK (N_TGT / 16)
#define ZCNT  (3 * (N_USER + 1))
#define ZTOT  (ZCNT + 5 * 128 + 1 + TB_W + TB_W + IB_W)
#define ZBLK  ((ZTOT + 255) / 256)

__global__ void mlp_kernel(const __half* __restrict__ xuc,
                           const float* __restrict__ W1, const float* __restrict__ b1,
                           const float* __restrict__ W2, const float* __restrict__ b2,
                           float* __restrict__ out) {
    if (blockIdx.x < ZBLK) {
        // head: restore the zero-invariant for the next call
        int i = blockIdx.x * blockDim.x + threadIdx.x;
        if (i < ZCNT) { ((int*)g_cnt)[i] = 0; return; }
        int j = i - ZCNT;
        if (j < 5 * 128) { g_bflag[j] = 0; return; }
        j -= 5 * 128;
        if (j < 1) { g_ticket = 0; return; }
        j -= 1;
        if (j < TB_W) { g_tbits[j] = 0; return; }
        j -= TB_W;
        if (j < TB_W) { g_nUbits[j] = 0; return; }
        j -= TB_W;
        if (j < IB_W) g_nIbits[j] = 0;
        return;
    }

    __shared__ float sW1[64 * H];
    __shared__ float sC[128];
    int t = threadIdx.x;
    #pragma unroll
    for (int i = 0; i < 8; i++)
        ((float4*)sW1)[t + 256 * i] = ((const float4*)W1)[t + 256 * i];
    if (t < 64) { sC[t] = b1[t]; sC[64 + t] = W2[t]; }
    __syncthreads();

    int lane = t & 31;
    int warp = (blockIdx.x - ZBLK) * 8 + (t >> 5);
    int t0 = warp * 2;
    uint2 xra = *(const uint2*)(xuc + (size_t)t0 * H + lane * 4);
    uint2 xrb = *(const uint2*)(xuc + (size_t)(t0 + 1) * H + lane * 4);
    float2 a0 = __half22float2(*(__half2*)&xra.x);
    float2 a1 = __half22float2(*(__half2*)&xra.y);
    float2 c0 = __half22float2(*(__half2*)&xrb.x);
    float2 c1 = __half22float2(*(__half2*)&xrb.y);
    float accA = 0.f, accB = 0.f;
    #pragma unroll 4
    for (int j = 0; j < 64; j++) {
        float4 w = *(const float4*)(sW1 + j * H + lane * 4);
        float pA = a0.x * w.x + a0.y * w.y + a1.x * w.z + a1.y * w.w;
        float pB = c0.x * w.x + c0.y * w.y + c1.x * w.z + c1.y * w.w;
        #pragma unroll
        for (int o = 16; o; o >>= 1) {
            pA += __shfl_xor_sync(0xffffffffu, pA, o);
            pB += __shfl_xor_sync(0xffffffffu, pB, o);
        }
        float bj = sC[j], wj = sC[64 + j];
        accA += fmaxf(pA + bj, 0.f) * wj;
        accB += fmaxf(pB + bj, 0.f) * wj;
    }
    if (lane == 0) {
        float bb2 = b2[0];
        out[t0]     = accA + bb2;
        out[t0 + 1] = accB + bb2;
    }
}

// ---------------------------------------------------------------------------
// Launch
// ---------------------------------------------------------------------------
extern "C" void kernel_launch(void* const* d_in, const int* in_sizes, int n_in,
                              void* d_out, int out_size) {
    const float* emb_user = (const float*)d_in[0];
    const float* emb_item = (const float*)d_in[1];
    const float* Wl       = (const float*)d_in[2];
    const float* bl       = (const float*)d_in[3];
    const float* Wr       = (const float*)d_in[4];
    const float* ln_g     = (const float*)d_in[5];
    const float* ln_b     = (const float*)d_in[6];
    const float* W1       = (const float*)d_in[7];
    const float* b1       = (const float*)d_in[8];
    const float* W2       = (const float*)d_in[9];
    const float* b2       = (const float*)d_in[10];
    const int* src_buys   = (const int*)d_in[11];
    const int* dst_buys   = (const int*)d_in[12];
    const int* src_rev    = (const int*)d_in[13];
    const int* dst_rev    = (const int*)d_in[14];
    const int* src_fol    = (const int*)d_in[15];
    const int* dst_fol    = (const int*)d_in[16];
    const int* target_ids = (const int*)d_in[17];
    float* out = (float*)d_out;

    __half *p_eu16, *p_ei16, *p_xu0h, *p_xi0h, *p_xufh, *p_aggU, *p_aggI;
    unsigned* p_wth;
    float* p_bias;
    int *p_off, *p_cmpU, *p_cmpI;
    cudaGetSymbolAddress((void**)&p_eu16, g_eu16);
    cudaGetSymbolAddress((void**)&p_ei16, g_ei16);
    cudaGetSymbolAddress((void**)&p_xu0h, g_xu0h);
    cudaGetSymbolAddress((void**)&p_xi0h, g_xi0h);
    cudaGetSymbolAddress((void**)&p_xufh, g_xufh);
    cudaGetSymbolAddress((void**)&p_aggU, g_aggU);
    cudaGetSymbolAddress((void**)&p_aggI, g_aggI);
    cudaGetSymbolAddress((void**)&p_wth,  g_wth);
    cudaGetSymbolAddress((void**)&p_bias, g_bias);
    cudaGetSymbolAddress((void**)&p_off,  g_off);
    cudaGetSymbolAddress((void**)&p_cmpU, g_cmpU);
    cudaGetSymbolAddress((void**)&p_cmpI, g_cmpI);

    const int* p_cntU = p_off + 3 * (N_USER + 1) + N_USER;
    const int* p_cntI = p_off + 4 * (N_USER + 1) + N_ITEM;

    const int smem_bytes = 3 * STAGEB;   // 107520
    cudaFuncSetAttribute(gemm_ln_kernel,
                         cudaFuncAttributeMaxDynamicSharedMemorySize, smem_bytes);

    // --- CSR + pruning chain (scratch pre-zeroed invariantly) ---
    flag_kernel<<<(N_TGT + 255) / 256, 256>>>(target_ids);
    count_prep_kernel<<<CBLK + PBLK, 256>>>(dst_buys,
                                            dst_rev, src_rev,
                                            dst_fol, src_fol,
                                            emb_user, emb_item, Wl, Wr, bl);
    scan_kernel<<<SCAN_BLOCKS, 1024>>>();
    fill_all_kernel<<<(3 * NE4 + 255) / 256, 256>>>(dst_buys, src_buys,
                                                    dst_rev, src_rev,
                                                    dst_fol, src_fol);

    // ===== layer 0 (pruned to needed nodes) =====
    {
        int nwarp = N_ITEM + 2 * N_USER;
        agg_l0_kernel<<<(nwarp * 32 + 255) / 256, 256>>>(p_eu16, p_ei16);

        GemmJob ji, ju;
        ji.out = p_xi0h; ji.A0 = p_ei16; ji.A1 = p_aggI;
        ji.ridx0 = p_cmpI; ji.ridx1 = p_cmpI; ji.ridxo = p_cmpI; ji.cnt = p_cntI;
        ji.Wt = p_wth; ji.bias = p_bias;
        ji.gam = ln_g + 1 * H; ji.bet = ln_b + 1 * H;
        ji.lda0 = H; ji.lda1 = H; ji.k0c = 2; ji.nchunk = 4; ji.nrows = N_ITEM;

        ju.out = p_xu0h; ju.A0 = p_eu16; ju.A1 = p_aggU;
        ju.ridx0 = p_cmpU; ju.ridx1 = p_cmpU; ju.ridxo = p_cmpU; ju.cnt = p_cntU;
        ju.Wt = p_wth + 128 * H; ju.bias = p_bias + 1 * H;
        ju.gam = ln_g + 0 * H; ju.bet = ln_b + 0 * H;
        ju.lda0 = H; ju.lda1 = 256; ju.k0c = 2; ju.nchunk = 6; ju.nrows = N_USER;

        int nbi = (N_ITEM + 127) / 128;
        int nbu = (N_USER + 127) / 128;
        gemm_ln_kernel<<<nbi + nbu, 256, smem_bytes>>>(ji, ju, nbi);
    }
    // ===== layer 1: only target rows =====
    {
        agg_tgt_kernel<<<(2 * N_TGT * 32 + 255) / 256, 256>>>(p_xi0h, p_xu0h, target_ids);

        GemmJob jt;
        jt.out = p_xufh; jt.A0 = p_xu0h; jt.A1 = p_aggU;
        jt.ridx0 = target_ids; jt.ridx1 = nullptr; jt.ridxo = nullptr; jt.cnt = nullptr;
        jt.Wt = p_wth + (128 + 192) * H; jt.bias = p_bias + 2 * H;
        jt.gam = ln_g + 2 * H; jt.bet = ln_b + 2 * H;
        jt.lda0 = H; jt.lda1 = 256; jt.k0c = 2; jt.nchunk = 6; jt.nrows = N_TGT;

        int nbt = N_TGT / 128;
        gemm_ln_kernel<<<nbt, 256, smem_bytes>>>(jt, jt, nbt);
    }

    mlp_kernel<<<ZBLK + MLP_BLK, 256>>>(p_xufh, W1, b1, W2, b2, out);
}

// round 14
// speedup vs baseline: 1.0309x; 1.0309x over previous
#include <cuda_runtime.h>
#include <cuda_fp16.h>
#include <cstdint>

#define N_USER 100000
#define N_ITEM 50000
#define NE     800000
#define NE4    (NE / 4)
#define H      128
#define N_TGT  8192

#if defined(__CUDA_ARCH__) && (__CUDA_ARCH__ >= 900)
#define GRID_DEP_SYNC() cudaGridDependencySynchronize()
#else
#define GRID_DEP_SYNC()
#endif

// ---------------------------------------------------------------------------
// Static device scratch (fp16 feature world)
// ---------------------------------------------------------------------------
__device__ __half g_eu16[N_USER * H];
__device__ __half g_ei16[N_ITEM * H];
__device__ __half g_xu0h[N_USER * H];
__device__ __half g_xi0h[N_ITEM * H];
__device__ __half g_xufh[N_TGT * H];
__device__ __half g_aggU[N_USER * 256];     // layer0: [mrev|mfol]; layer1: compact rows
__device__ __half g_aggI[N_ITEM * H];
__device__ unsigned g_wth[(128 + 192 + 192) * H];   // fp16 half2-packed K-major weights
__device__ float g_bias[3 * H];

// CSR + scan scratch. INVARIANT: g_cnt/g_bflag/g_ticket/bit arrays are ZERO at
// entry of every call (zero-init at load; re-zeroed by mlp head blocks).
__device__ int g_cnt[3][N_USER + 1];
__device__ int g_off[5][N_USER + 1];
__device__ int g_cur[3][N_USER];
__device__ int g_csr[3][NE];
__device__ int g_bsum[5][128];
__device__ int g_bflag[5 * 128];
__device__ int g_ticket;

// pruning flags as bitmasks (L1-resident)
#define TB_W 4096
#define IB_W 2048
__device__ int g_tbits[TB_W];
__device__ int g_nUbits[TB_W];
__device__ int g_nIbits[IB_W];

__device__ int g_cmpU[N_USER];
__device__ int g_cmpI[N_ITEM];

// graph ids: 0 = buys (dst=item), 1 = rev (dst=user), 2 = fol (dst=user)

__device__ __forceinline__ int getbit(const int* a, int i) {
    return (__ldg(&a[i >> 5]) >> (i & 31)) & 1;
}
__device__ __forceinline__ void setbit(int* a, int i) {
    int w = i >> 5, m = 1 << (i & 31);
    if (!(a[w] & m)) atomicOr(&a[w], m);
}

__device__ __forceinline__ unsigned smem_u32(const void* p) {
    return (unsigned)__cvta_generic_to_shared(p);
}
#define CP16(dst, src, sz) \
    asm volatile("cp.async.cg.shared.global [%0], [%1], 16, %2;\n" \
                 :: "r"(dst), "l"(src), "r"(sz))

// ---------------------------------------------------------------------------
// K1: flag targets (tiny; plain launch)
// ---------------------------------------------------------------------------
__global__ void flag_kernel(const int* __restrict__ tgt) {
    int i = blockIdx.x * blockDim.x + threadIdx.x;
    if (i < N_TGT) {
        int t = tgt[i];
        setbit(g_tbits, t);
        setbit(g_nUbits, t);
    }
}

// ---------------------------------------------------------------------------
// K2: fused [degree count + need flags] ++ [emb->fp16 + weight/bias prep]
// ---------------------------------------------------------------------------
#define NU8   (N_USER * H / 8)
#define NI8   (N_ITEM * H / 8)
#define WTOT  ((128 + 192 + 192) * H)
#define PREPN (NU8 + NI8 + WTOT + 3 * H)
#define CBLK  ((3 * NE4 + 255) / 256)
#define PBLK  ((PREPN + 255) / 256)

__device__ __forceinline__ uint4 pack8(float4 a, float4 b) {
    __half2 h0 = __floats2half2_rn(a.x, a.y);
    __half2 h1 = __floats2half2_rn(a.z, a.w);
    __half2 h2 = __floats2half2_rn(b.x, b.y);
    __half2 h3 = __floats2half2_rn(b.z, b.w);
    uint4 u;
    u.x = *(unsigned*)&h0; u.y = *(unsigned*)&h1;
    u.z = *(unsigned*)&h2; u.w = *(unsigned*)&h3;
    return u;
}
__device__ __forceinline__ float wval_item(const float* Wl, const float* Wr, int k, int j) {
    return (k < 128) ? Wr[(0 * H + j) * H + k] : Wl[(0 * H + j) * H + (k - 128)];
}
__device__ __forceinline__ float wval_user(const float* Wl, const float* Wr, int l, int k, int j) {
    if (k < 128) return Wr[((l * 3 + 1) * H + j) * H + k] + Wr[((l * 3 + 2) * H + j) * H + k];
    if (k < 256) return Wl[((l * 3 + 1) * H + j) * H + (k - 128)];
    return Wl[((l * 3 + 2) * H + j) * H + (k - 256)];
}

__global__ void count_prep_kernel(const int* __restrict__ d0,
                                  const int* __restrict__ d1, const int* __restrict__ s1,
                                  const int* __restrict__ d2, const int* __restrict__ s2,
                                  const float* __restrict__ eu, const float* __restrict__ ei,
                                  const float* __restrict__ Wl, const float* __restrict__ Wr,
                                  const float* __restrict__ bl) {
    GRID_DEP_SYNC();
    if (blockIdx.x < CBLK) {
        int i = blockIdx.x * blockDim.x + threadIdx.x;
        if (i >= 3 * NE4) return;
        int g = i / NE4, j = i % NE4;
        if (g == 0) {
            int4 v = ((const int4*)d0)[j];
            atomicAdd(&g_cnt[0][v.x], 1);
            atomicAdd(&g_cnt[0][v.y], 1);
            atomicAdd(&g_cnt[0][v.z], 1);
            atomicAdd(&g_cnt[0][v.w], 1);
        } else if (g == 1) {
            int4 d = ((const int4*)d1)[j];
            int4 s = ((const int4*)s1)[j];
            atomicAdd(&g_cnt[1][d.x], 1);
            atomicAdd(&g_cnt[1][d.y], 1);
            atomicAdd(&g_cnt[1][d.z], 1);
            atomicAdd(&g_cnt[1][d.w], 1);
            if (getbit(g_tbits, d.x)) setbit(g_nIbits, s.x);
            if (getbit(g_tbits, d.y)) setbit(g_nIbits, s.y);
            if (getbit(g_tbits, d.z)) setbit(g_nIbits, s.z);
            if (getbit(g_tbits, d.w)) setbit(g_nIbits, s.w);
        } else {
            int4 d = ((const int4*)d2)[j];
            int4 s = ((const int4*)s2)[j];
            atomicAdd(&g_cnt[2][d.x], 1);
            atomicAdd(&g_cnt[2][d.y], 1);
            atomicAdd(&g_cnt[2][d.z], 1);
            atomicAdd(&g_cnt[2][d.w], 1);
            if (getbit(g_tbits, d.x)) setbit(g_nUbits, s.x);
            if (getbit(g_tbits, d.y)) setbit(g_nUbits, s.y);
            if (getbit(g_tbits, d.z)) setbit(g_nUbits, s.z);
            if (getbit(g_tbits, d.w)) setbit(g_nUbits, s.w);
        }
        return;
    }
    // ---- prep part ----
    int i = (blockIdx.x - CBLK) * blockDim.x + threadIdx.x;
    if (i < NU8) {
        float4 a = ((const float4*)eu)[2 * i], b = ((const float4*)eu)[2 * i + 1];
        ((uint4*)g_eu16)[i] = pack8(a, b);
        return;
    }
    int j = i - NU8;
    if (j < NI8) {
        float4 a = ((const float4*)ei)[2 * j], b = ((const float4*)ei)[2 * j + 1];
        ((uint4*)g_ei16)[j] = pack8(a, b);
        return;
    }
    j -= NI8;
    if (j < WTOT) {
        float v0, v1;
        if (j < 128 * H) {
            int k2 = j >> 7, c = j & 127;
            v0 = wval_item(Wl, Wr, 2 * k2, c);
            v1 = wval_item(Wl, Wr, 2 * k2 + 1, c);
        } else {
            int rel = j - 128 * H;
            int l = (rel < 192 * H) ? 0 : 1;
            if (l == 1) rel -= 192 * H;
            int k2 = rel >> 7, c = rel & 127;
            v0 = wval_user(Wl, Wr, l, 2 * k2, c);
            v1 = wval_user(Wl, Wr, l, 2 * k2 + 1, c);
        }
        __half2 h = __floats2half2_rn(v0, v1);
        g_wth[j] = *(unsigned*)&h;
        return;
    }
    j -= WTOT;
    if (j < 3 * H) {
        int slot = j >> 7, c = j & 127;
        float b;
        if (slot == 0)      b = bl[0 * H + c];
        else if (slot == 1) b = bl[1 * H + c] + bl[2 * H + c];
        else                b = bl[(3 + 1) * H + c] + bl[(3 + 2) * H + c];
        g_bias[j] = b;
    }
}

// ---------------------------------------------------------------------------
// K3: single-pass scan over 5 rows with ticket-ordered parallel lookback.
// ---------------------------------------------------------------------------
#define NB_I 49
#define NB_U 98
#define SCAN_BLOCKS (NB_I + NB_U + NB_U + NB_U + NB_I)

__device__ __forceinline__ int scan_n(int g) {
    return (g == 0 || g == 4) ? N_ITEM : N_USER;
}

__global__ void scan_kernel() {
    GRID_DEP_SYNC();
    __shared__ int s_g, s_b;
    __shared__ int warp_sums[32];
    __shared__ int sw[4];
    __shared__ int s_base;

    if (threadIdx.x == 0) {
        int v = atomicAdd(&g_ticket, 1);
        int g, b;
        if (v < NB_I)                         { g = 0; b = v; }
        else if (v < NB_I + NB_U)             { g = 1; b = v - NB_I; }
        else if (v < NB_I + 2 * NB_U)         { g = 2; b = v - NB_I - NB_U; }
        else if (v < NB_I + 3 * NB_U)         { g = 3; b = v - NB_I - 2 * NB_U; }
        else                                  { g = 4; b = v - NB_I - 3 * NB_U; }
        s_g = g; s_b = b;
    }
    __syncthreads();
    int g = s_g, b = s_b;
    int n = scan_n(g);
    int nb = (g == 0 || g == 4) ? NB_I : NB_U;

    int i = b * 1024 + (int)threadIdx.x;
    int v;
    if (i >= n) v = 0;
    else if (g < 3) v = g_cnt[g][i];
    else if (g == 3) v = getbit(g_nUbits, i);
    else v = getbit(g_nIbits, i);

    int lane = threadIdx.x & 31, wid = threadIdx.x >> 5;
    int x = v;
    #pragma unroll
    for (int s = 1; s < 32; s <<= 1) {
        int y = __shfl_up_sync(0xffffffffu, x, s);
        if (lane >= s) x += y;
    }
    if (lane == 31) warp_sums[wid] = x;
    __syncthreads();
    if (wid == 0) {
        int w = warp_sums[lane];
        int xw = w;
        #pragma unroll
        for (int s = 1; s < 32; s <<= 1) {
            int y = __shfl_up_sync(0xffffffffu, xw, s);
            if (lane >= s) xw += y;
        }
        warp_sums[lane] = xw - w;
    }
    __syncthreads();
    int incl = x + warp_sums[wid];

    if (threadIdx.x == 1023) {
        g_bsum[g][b] = incl;
        __threadfence();
        atomicExch(&g_bflag[g * 128 + b], 1);
    }

    if (threadIdx.x < 128) {
        int j = threadIdx.x;
        int pv = 0;
        if (j < b) {
            while (atomicAdd(&g_bflag[g * 128 + j], 0) == 0) { }
            pv = g_bsum[g][j];
        }
        #pragma unroll
        for (int o = 16; o; o >>= 1) pv += __shfl_xor_sync(0xffffffffu, pv, o);
        if (lane == 0) sw[j >> 5] = pv;
    }
    __syncthreads();
    if (threadIdx.x == 0) s_base = sw[0] + sw[1] + sw[2] + sw[3];
    __syncthreads();
    int base = s_base;

    if (threadIdx.x == 1023 && b == nb - 1) g_off[g][n] = base + incl;
    if (i >= n) return;
    int val = base + incl - v;
    if (g < 3) {
        g_off[g][i] = val;
        g_cur[g][i] = val;
    } else if (g == 3) {
        if (v) g_cmpU[val] = i;
    } else {
        if (v) g_cmpI[val] = i;
    }
}

// ---------------------------------------------------------------------------
// K4: filtered fill — only edges whose dst node is ever read downstream.
// ---------------------------------------------------------------------------
__global__ void fill_all_kernel(const int* __restrict__ d0, const int* __restrict__ s0,
                                const int* __restrict__ d1, const int* __restrict__ s1,
                                const int* __restrict__ d2, const int* __restrict__ s2) {
    GRID_DEP_SYNC();
    int i = blockIdx.x * blockDim.x + threadIdx.x;
    if (i >= 3 * NE4) return;
    int g = i / NE4, j = i % NE4;
    const int* d = (g == 0) ? d0 : (g == 1) ? d1 : d2;
    const int* s = (g == 0) ? s0 : (g == 1) ? s1 : s2;
    const int* need = (g == 0) ? g_nIbits : g_nUbits;
    int4 dv = ((const int4*)d)[j];
    int4 sv = ((const int4*)s)[j];
    if (getbit(need, dv.x)) g_csr[g][atomicAdd(&g_cur[g][dv.x], 1)] = sv.x;
    if (getbit(need, dv.y)) g_csr[g][atomicAdd(&g_cur[g][dv.y], 1)] = sv.y;
    if (getbit(need, dv.z)) g_csr[g][atomicAdd(&g_cur[g][dv.z], 1)] = sv.z;
    if (getbit(need, dv.w)) g_csr[g][atomicAdd(&g_cur[g][dv.w], 1)] = sv.w;
}

// ---------------------------------------------------------------------------
// Gather-mean over fp16 rows (fp32 accumulate, strict index order).
// ---------------------------------------------------------------------------
__device__ __forceinline__ void acc4(float4& a, uint2 u) {
    __half2 h0 = *(__half2*)&u.x, h1 = *(__half2*)&u.y;
    float2 f0 = __half22float2(h0), f1 = __half22float2(h1);
    a.x += f0.x; a.y += f0.y; a.z += f1.x; a.w += f1.y;
}

__device__ __forceinline__ void agg_one(int g, int node, int lane,
                                        const __half* __restrict__ src,
                                        __half* __restrict__ dst) {
    int s = g_off[g][node], e = g_off[g][node + 1];
    const int* lst = g_csr[g];
    float4 acc = make_float4(0.f, 0.f, 0.f, 0.f);
    int i = s;
    for (; i + 8 <= e; i += 8) {
        uint2 v0 = *(const uint2*)(src + (size_t)lst[i]     * H + lane * 4);
        uint2 v1 = *(const uint2*)(src + (size_t)lst[i + 1] * H + lane * 4);
        uint2 v2 = *(const uint2*)(src + (size_t)lst[i + 2] * H + lane * 4);
        uint2 v3 = *(const uint2*)(src + (size_t)lst[i + 3] * H + lane * 4);
        uint2 v4 = *(const uint2*)(src + (size_t)lst[i + 4] * H + lane * 4);
        uint2 v5 = *(const uint2*)(src + (size_t)lst[i + 5] * H + lane * 4);
        uint2 v6 = *(const uint2*)(src + (size_t)lst[i + 6] * H + lane * 4);
        uint2 v7 = *(const uint2*)(src + (size_t)lst[i + 7] * H + lane * 4);
        acc4(acc, v0); acc4(acc, v1); acc4(acc, v2); acc4(acc, v3);
        acc4(acc, v4); acc4(acc, v5); acc4(acc, v6); acc4(acc, v7);
    }
    for (; i + 4 <= e; i += 4) {
        uint2 v0 = *(const uint2*)(src + (size_t)lst[i]     * H + lane * 4);
        uint2 v1 = *(const uint2*)(src + (size_t)lst[i + 1] * H + lane * 4);
        uint2 v2 = *(const uint2*)(src + (size_t)lst[i + 2] * H + lane * 4);
        uint2 v3 = *(const uint2*)(src + (size_t)lst[i + 3] * H + lane * 4);
        acc4(acc, v0); acc4(acc, v1); acc4(acc, v2); acc4(acc, v3);
    }
    for (; i < e; i++) {
        uint2 v0 = *(const uint2*)(src + (size_t)lst[i] * H + lane * 4);
        acc4(acc, v0);
    }
    float inv = (e > s) ? 1.0f / (float)(e - s) : 0.0f;
    __half2 o0 = __floats2half2_rn(acc.x * inv, acc.y * inv);
    __half2 o1 = __floats2half2_rn(acc.z * inv, acc.w * inv);
    uint2 o; o.x = *(unsigned*)&o0; o.y = *(unsigned*)&o1;
    *(uint2*)(dst + lane * 4) = o;
}

__global__ void agg_l0_kernel(const __half* __restrict__ eu,
                              const __half* __restrict__ ei) {
    GRID_DEP_SYNC();
    int warp = (blockIdx.x * blockDim.x + threadIdx.x) >> 5;
    int lane = threadIdx.x & 31;
    if (warp < N_ITEM) {
        int nI = __ldg(&g_off[4][N_ITEM]);
        if (warp >= nI) return;
        int node = g_cmpI[warp];
        agg_one(0, node, lane, eu, g_aggI + (size_t)node * H);
    } else {
        int w2 = warp - N_ITEM;
        int nU = __ldg(&g_off[3][N_USER]);
        if (w2 < N_USER) {
            if (w2 >= nU) return;
            int node = g_cmpU[w2];
            agg_one(1, node, lane, ei, g_aggU + (size_t)node * 256);
        } else {
            w2 -= N_USER;
            if (w2 >= N_USER || w2 >= nU) return;
            int node = g_cmpU[w2];
            agg_one(2, node, lane, eu, g_aggU + (size_t)node * 256 + 128);
        }
    }
}

__global__ void agg_tgt_kernel(const __half* __restrict__ xi0,
                               const __half* __restrict__ xu0,
                               const int* __restrict__ tgt) {
    GRID_DEP_SYNC();
    int warp = (blockIdx.x * blockDim.x + threadIdx.x) >> 5;
    int lane = threadIdx.x & 31;
    if (warp >= 2 * N_TGT) return;
    int pos = warp & (N_TGT - 1);
    int node = tgt[pos];
    if (warp < N_TGT)
        agg_one(1, node, lane, xi0, g_aggU + (size_t)pos * 256);
    else
        agg_one(2, node, lane, xu0, g_aggU + (size_t)pos * 256 + 128);
}

// ---------------------------------------------------------------------------
// FP16 mma.sync tensor-core GEMM (cp.async 3-stage) + fused LN + ReLU.
// (tcgen05 unavailable: harness PTX targets compute_103, not compute_103a.)
// ---------------------------------------------------------------------------
#define ASTRIDE 36
#define WSTRIDE 136
#define OSTRIDE 132
#define STAGEB  35840

extern __shared__ char g_smraw[];

struct GemmJob {
    __half* out;
    const __half* A0;
    const __half* A1;
    const int* ridx0;
    const int* ridx1;
    const int* ridxo;
    const int* cnt;
    const unsigned* Wt;
    const float* bias;
    const float* gam;
    const float* bet;
    int lda0, lda1, k0c, nchunk, nrows;
};

__device__ __forceinline__ void mma_f16(float c[4], const unsigned a[4], const unsigned b[2]) {
    asm volatile(
        "mma.sync.aligned.m16n8k16.row.col.f32.f16.f16.f32 "
        "{%0,%1,%2,%3}, {%4,%5,%6,%7}, {%8,%9}, {%0,%1,%2,%3};"
        : "+f"(c[0]), "+f"(c[1]), "+f"(c[2]), "+f"(c[3])
        : "r"(a[0]), "r"(a[1]), "r"(a[2]), "r"(a[3]), "r"(b[0]), "r"(b[1]));
}

__global__ void __launch_bounds__(256, 2) gemm_ln_kernel(GemmJob j0, GemmJob j1, int split) {
    GRID_DEP_SYNC();
    GemmJob J = (blockIdx.x < (unsigned)split) ? j0 : j1;
    int bid = (blockIdx.x < (unsigned)split) ? blockIdx.x : blockIdx.x - split;
    int row0 = bid * 128;

    int nrows = J.cnt ? __ldg(J.cnt) : J.nrows;
    if (row0 >= nrows) return;

    int t = threadIdx.x;
    int lane = t & 31;
    int wid = t >> 5;
    int warp_m = wid & 3;
    int warp_n = wid >> 2;
    int gid = lane >> 2;
    int tig = lane & 3;

    float c[2][8][4];
    #pragma unroll
    for (int nt = 0; nt < 8; nt++) {
        int col = warp_n * 64 + nt * 8 + 2 * tig;
        float b0 = J.bias[col], b1 = J.bias[col + 1];
        #pragma unroll
        for (int mt = 0; mt < 2; mt++) {
            c[mt][nt][0] = b0; c[mt][nt][1] = b1;
            c[mt][nt][2] = b0; c[mt][nt][3] = b1;
        }
    }

    auto load_chunk = [&](int ck, int st) {
        if (ck < J.nchunk) {
            const __half* A; int lda, cb; const int* ridx;
            if (ck < J.k0c) { A = J.A0; lda = J.lda0; cb = ck * 64; ridx = J.ridx0; }
            else            { A = J.A1; lda = J.lda1; cb = (ck - J.k0c) * 64; ridx = J.ridx1; }
            unsigned* As = (unsigned*)(g_smraw + st * STAGEB);
            #pragma unroll
            for (int i2 = 0; i2 < 4; i2++) {
                int idx = t + 256 * i2;
                int r = idx >> 3, u = idx & 7;
                int base = row0 + r;
                int ok = (base < nrows);
                if (!ok) base = row0;
                int row = ridx ? __ldg(ridx + base) : base;
                const __half* src = A + (size_t)row * lda + cb + u * 8;
                CP16(smem_u32(As + r * ASTRIDE + u * 4), src, ok ? 16 : 0);
            }
            unsigned* Ws = (unsigned*)(g_smraw + st * STAGEB + 128 * ASTRIDE * 4);
            #pragma unroll
            for (int i2 = 0; i2 < 4; i2++) {
                int idx = t + 256 * i2;
                int rr = idx >> 5, u = idx & 31;
                const unsigned* src = J.Wt + (size_t)(ck * 32 + rr) * H + u * 4;
                CP16(smem_u32(Ws + rr * WSTRIDE + u * 4), src, 16);
            }
        }
        asm volatile("cp.async.commit_group;\n" ::);
    };

    load_chunk(0, 0);
    load_chunk(1, 1);

    for (int ck = 0; ck < J.nchunk; ck++) {
        asm volatile("cp.async.wait_group 1;\n" ::);
        __syncthreads();
        load_chunk(ck + 2, (ck + 2) % 3);

        int st = ck % 3;
        const unsigned* As = (const unsigned*)(g_smraw + st * STAGEB);
        const unsigned* Ws = (const unsigned*)(g_smraw + st * STAGEB + 128 * ASTRIDE * 4);
        #pragma unroll
        for (int ks = 0; ks < 4; ks++) {
            int k2 = ks * 8;
            unsigned a[2][4];
            #pragma unroll
            for (int mt = 0; mt < 2; mt++) {
                int r = warp_m * 32 + mt * 16 + gid;
                a[mt][0] = As[r * ASTRIDE + k2 + tig];
                a[mt][1] = As[(r + 8) * ASTRIDE + k2 + tig];
                a[mt][2] = As[r * ASTRIDE + k2 + tig + 4];
                a[mt][3] = As[(r + 8) * ASTRIDE + k2 + tig + 4];
            }
            unsigned b[8][2];
            #pragma unroll
            for (int nt = 0; nt < 8; nt++) {
                int cc = warp_n * 64 + nt * 8 + gid;
                b[nt][0] = Ws[(k2 + tig) * WSTRIDE + cc];
                b[nt][1] = Ws[(k2 + tig + 4) * WSTRIDE + cc];
            }
            #pragma unroll
            for (int mt = 0; mt < 2; mt++)
                #pragma unroll
                for (int nt = 0; nt < 8; nt++)
                    mma_f16(c[mt][nt], a[mt], b[nt]);
        }
    }

    // ---- epilogue: stage fp32 to smem, fused LayerNorm + ReLU, fp16 out ----
    asm volatile("cp.async.wait_group 0;\n" ::);
    __syncthreads();
    float* Osm = (float*)g_smraw;
    #pragma unroll
    for (int mt = 0; mt < 2; mt++) {
        #pragma unroll
        for (int nt = 0; nt < 8; nt++) {
            int col = warp_n * 64 + nt * 8 + 2 * tig;
            int r = warp_m * 32 + mt * 16 + gid;
            *(float2*)(Osm + r * OSTRIDE + col)       = make_float2(c[mt][nt][0], c[mt][nt][1]);
            *(float2*)(Osm + (r + 8) * OSTRIDE + col) = make_float2(c[mt][nt][2], c[mt][nt][3]);
        }
    }
    __syncthreads();

    float4 gg = *(const float4*)(J.gam + lane * 4);
    float4 bb = *(const float4*)(J.bet + lane * 4);
    #pragma unroll
    for (int i = 0; i < 16; i++) {
        int r = wid * 16 + i;
        int base = row0 + r;
        if (base >= nrows) break;
        float4 v = *(float4*)(Osm + r * OSTRIDE + lane * 4);
        float s1 = v.x + v.y + v.z + v.w;
        float s2 = v.x * v.x + v.y * v.y + v.z * v.z + v.w * v.w;
        #pragma unroll
        for (int o = 16; o; o >>= 1) {
            s1 += __shfl_xor_sync(0xffffffffu, s1, o);
            s2 += __shfl_xor_sync(0xffffffffu, s2, o);
        }
        float mu = s1 * (1.0f / H);
        float var = s2 * (1.0f / H) - mu * mu;
        float rs = rsqrtf(var + 1e-5f);
        float ox = fmaxf((v.x - mu) * rs * gg.x + bb.x, 0.f);
        float oy = fmaxf((v.y - mu) * rs * gg.y + bb.y, 0.f);
        float oz = fmaxf((v.z - mu) * rs * gg.z + bb.z, 0.f);
        float ow = fmaxf((v.w - mu) * rs * gg.w + bb.w, 0.f);
        __half2 h0 = __floats2half2_rn(ox, oy);
        __half2 h1 = __floats2half2_rn(oz, ow);
        uint2 o; o.x = *(unsigned*)&h0; o.y = *(unsigned*)&h1;
        int orow = J.ridxo ? __ldg(J.ridxo + base) : base;
        *(uint2*)(J.out + (size_t)orow * H + lane * 4) = o;
    }
}

// ---------------------------------------------------------------------------
// K-last: zero-head blocks, then MLP head (W1/b1/W2 staged in smem).
// ---------------------------------------------------------------------------
#define MLP_BLK (N_TGT / 16)
#define ZCNT  (3 * (N_USER + 1))
#define ZTOT  (ZCNT + 5 * 128 + 1 + TB_W + TB_W + IB_W)
#define ZBLK  ((ZTOT + 255) / 256)

__global__ void mlp_kernel(const __half* __restrict__ xuc,
                           const float* __restrict__ W1, const float* __restrict__ b1,
                           const float* __restrict__ W2, const float* __restrict__ b2,
                           float* __restrict__ out) {
    GRID_DEP_SYNC();
    if (blockIdx.x < ZBLK) {
        // restore the zero-invariant for the next call
        int i = blockIdx.x * blockDim.x + threadIdx.x;
        if (i < ZCNT) { ((int*)g_cnt)[i] = 0; return; }
        int j = i - ZCNT;
        if (j < 5 * 128) { g_bflag[j] = 0; return; }
        j -= 5 * 128;
        if (j < 1) { g_ticket = 0; return; }
        j -= 1;
        if (j < TB_W) { g_tbits[j] = 0; return; }
        j -= TB_W;
        if (j < TB_W) { g_nUbits[j] = 0; return; }
        j -= TB_W;
        if (j < IB_W) g_nIbits[j] = 0;
        return;
    }

    __shared__ float sW1[64 * H];
    __shared__ float sC[128];
    int t = threadIdx.x;
    #pragma unroll
    for (int i = 0; i < 8; i++)
        ((float4*)sW1)[t + 256 * i] = ((const float4*)W1)[t + 256 * i];
    if (t < 64) { sC[t] = b1[t]; sC[64 + t] = W2[t]; }
    __syncthreads();

    int lane = t & 31;
    int warp = (blockIdx.x - ZBLK) * 8 + (t >> 5);
    int t0 = warp * 2;
    uint2 xra = *(const uint2*)(xuc + (size_t)t0 * H + lane * 4);
    uint2 xrb = *(const uint2*)(xuc + (size_t)(t0 + 1) * H + lane * 4);
    float2 a0 = __half22float2(*(__half2*)&xra.x);
    float2 a1 = __half22float2(*(__half2*)&xra.y);
    float2 c0 = __half22float2(*(__half2*)&xrb.x);
    float2 c1 = __half22float2(*(__half2*)&xrb.y);
    float accA = 0.f, accB = 0.f;
    #pragma unroll 4
    for (int j = 0; j < 64; j++) {
        float4 w = *(const float4*)(sW1 + j * H + lane * 4);
        float pA = a0.x * w.x + a0.y * w.y + a1.x * w.z + a1.y * w.w;
        float pB = c0.x * w.x + c0.y * w.y + c1.x * w.z + c1.y * w.w;
        #pragma unroll
        for (int o = 16; o; o >>= 1) {
            pA += __shfl_xor_sync(0xffffffffu, pA, o);
            pB += __shfl_xor_sync(0xffffffffu, pB, o);
        }
        float bj = sC[j], wj = sC[64 + j];
        accA += fmaxf(pA + bj, 0.f) * wj;
        accB += fmaxf(pB + bj, 0.f) * wj;
    }
    if (lane == 0) {
        float bb2 = b2[0];
        out[t0]     = accA + bb2;
        out[t0 + 1] = accB + bb2;
    }
}

// ---------------------------------------------------------------------------
// Launch (PDL on all dependent launches)
// ---------------------------------------------------------------------------
template <typename... Args>
static inline void launch_pdl(void (*kern)(Args...), int grid, int block,
                              size_t smem, Args... args) {
    cudaLaunchConfig_t cfg = {};
    cudaLaunchAttribute attr[1];
    attr[0].id = cudaLaunchAttributeProgrammaticStreamSerialization;
    attr[0].val.programmaticStreamSerializationAllowed = 1;
    cfg.gridDim = dim3(grid, 1, 1);
    cfg.blockDim = dim3(block, 1, 1);
    cfg.dynamicSmemBytes = smem;
    cfg.stream = 0;
    cfg.attrs = attr;
    cfg.numAttrs = 1;
    cudaLaunchKernelEx(&cfg, kern, args...);
}

extern "C" void kernel_launch(void* const* d_in, const int* in_sizes, int n_in,
                              void* d_out, int out_size) {
    const float* emb_user = (const float*)d_in[0];
    const float* emb_item = (const float*)d_in[1];
    const float* Wl       = (const float*)d_in[2];
    const float* bl       = (const float*)d_in[3];
    const float* Wr       = (const float*)d_in[4];
    const float* ln_g     = (const float*)d_in[5];
    const float* ln_b     = (const float*)d_in[6];
    const float* W1       = (const float*)d_in[7];
    const float* b1       = (const float*)d_in[8];
    const float* W2       = (const float*)d_in[9];
    const float* b2       = (const float*)d_in[10];
    const int* src_buys   = (const int*)d_in[11];
    const int* dst_buys   = (const int*)d_in[12];
    const int* src_rev    = (const int*)d_in[13];
    const int* dst_rev    = (const int*)d_in[14];
    const int* src_fol    = (const int*)d_in[15];
    const int* dst_fol    = (const int*)d_in[16];
    const int* target_ids = (const int*)d_in[17];
    float* out = (float*)d_out;

    __half *p_eu16, *p_ei16, *p_xu0h, *p_xi0h, *p_xufh, *p_aggU, *p_aggI;
    unsigned* p_wth;
    float* p_bias;
    int *p_off, *p_cmpU, *p_cmpI;
    cudaGetSymbolAddress((void**)&p_eu16, g_eu16);
    cudaGetSymbolAddress((void**)&p_ei16, g_ei16);
    cudaGetSymbolAddress((void**)&p_xu0h, g_xu0h);
    cudaGetSymbolAddress((void**)&p_xi0h, g_xi0h);
    cudaGetSymbolAddress((void**)&p_xufh, g_xufh);
    cudaGetSymbolAddress((void**)&p_aggU, g_aggU);
    cudaGetSymbolAddress((void**)&p_aggI, g_aggI);
    cudaGetSymbolAddress((void**)&p_wth,  g_wth);
    cudaGetSymbolAddress((void**)&p_bias, g_bias);
    cudaGetSymbolAddress((void**)&p_off,  g_off);
    cudaGetSymbolAddress((void**)&p_cmpU, g_cmpU);
    cudaGetSymbolAddress((void**)&p_cmpI, g_cmpI);

    const int* p_cntU = p_off + 3 * (N_USER + 1) + N_USER;
    const int* p_cntI = p_off + 4 * (N_USER + 1) + N_ITEM;

    const int smem_bytes = 3 * STAGEB;   // 107520
    cudaFuncSetAttribute(gemm_ln_kernel,
                         cudaFuncAttributeMaxDynamicSharedMemorySize, smem_bytes);

    // --- CSR + pruning chain (scratch pre-zeroed invariantly) ---
    flag_kernel<<<(N_TGT + 255) / 256, 256>>>(target_ids);
    launch_pdl(count_prep_kernel, CBLK + PBLK, 256, 0,
               dst_buys, dst_rev, src_rev, dst_fol, src_fol,
               emb_user, emb_item, Wl, Wr, bl);
    launch_pdl(scan_kernel, SCAN_BLOCKS, 1024, (size_t)0);
    launch_pdl(fill_all_kernel, (3 * NE4 + 255) / 256, 256, 0,
               dst_buys, src_buys, dst_rev, src_rev, dst_fol, src_fol);

    // ===== layer 0 (pruned to needed nodes) =====
    {
        int nwarp = N_ITEM + 2 * N_USER;
        launch_pdl(agg_l0_kernel, (nwarp * 32 + 255) / 256, 256, 0,
                   (const __half*)p_eu16, (const __half*)p_ei16);

        GemmJob ji, ju;
        ji.out = p_xi0h; ji.A0 = p_ei16; ji.A1 = p_aggI;
        ji.ridx0 = p_cmpI; ji.ridx1 = p_cmpI; ji.ridxo = p_cmpI; ji.cnt = p_cntI;
        ji.Wt = p_wth; ji.bias = p_bias;
        ji.gam = ln_g + 1 * H; ji.bet = ln_b + 1 * H;
        ji.lda0 = H; ji.lda1 = H; ji.k0c = 2; ji.nchunk = 4; ji.nrows = N_ITEM;

        ju.out = p_xu0h; ju.A0 = p_eu16; ju.A1 = p_aggU;
        ju.ridx0 = p_cmpU; ju.ridx1 = p_cmpU; ju.ridxo = p_cmpU; ju.cnt = p_cntU;
        ju.Wt = p_wth + 128 * H; ju.bias = p_bias + 1 * H;
        ju.gam = ln_g + 0 * H; ju.bet = ln_b + 0 * H;
        ju.lda0 = H; ju.lda1 = 256; ju.k0c = 2; ju.nchunk = 6; ju.nrows = N_USER;

        int nbi = (N_ITEM + 127) / 128;
        int nbu = (N_USER + 127) / 128;
        launch_pdl(gemm_ln_kernel, nbi + nbu, 256, (size_t)smem_bytes, ji, ju, nbi);
    }
    // ===== layer 1: only target rows =====
    {
        launch_pdl(agg_tgt_kernel, (2 * N_TGT * 32 + 255) / 256, 256, 0,
                   (const __half*)p_xi0h, (const __half*)p_xu0h, target_ids);

        GemmJob jt;
        jt.out = p_xufh; jt.A0 = p_xu0h; jt.A1 = p_aggU;
        jt.ridx0 = target_ids; jt.ridx1 = nullptr; jt.ridxo = nullptr; jt.cnt = nullptr;
        jt.Wt = p_wth + (128 + 192) * H; jt.bias = p_bias + 2 * H;
        jt.gam = ln_g + 2 * H; jt.bet = ln_b + 2 * H;
        jt.lda0 = H; jt.lda1 = 256; jt.k0c = 2; jt.nchunk = 6; jt.nrows = N_TGT;

        int nbt = N_TGT / 128;
        launch_pdl(gemm_ln_kernel, nbt, 256, (size_t)smem_bytes, jt, jt, nbt);
    }

    launch_pdl(mlp_kernel, ZBLK + MLP_BLK, 256, 0,
               (const __half*)p_xufh, W1, b1, W2, b2, out);
}